// round 12
// baseline (speedup 1.0000x reference)
#include <cuda_runtime.h>
#include <cuda_fp16.h>

// QuConv: out = Re(U X U^dagger), U = Up^{kron 6}, Up 4x4 complex from 5
// weights, X real [4,4096,4096]. Output: float32 real parts (67,108,864 el).
//
// Up = D*G*A per digit; all six per-digit diagonals D commute with every
// other digit's G*A, so the full transform = (prod G_k A_k) * D_tot with
// D_tot a single 4096-entry diagonal phase table (g_D). Butterflies apply
// A (4 packed ops/pair) then G (4 ops/pair) per digit = 8 vs 12 fused.
// Column-side phase conj(ddtot[j]) is folded into kA1's load (4 ops/pair,
// once); row-side phase enters kA2r's Re() epilogue (2 ops/pair).
//
// Passes (intermediate g_S is fp16 complex; rel_err budget 1e-3, measured
// fp16 pipeline at 2.9e-4):
//   kJ  : ALL 6 column digits (conj side), full 4096-row in 64KB smem,
//         x(fp32) -> g_S(fp16). XOR-swizzled smem, conflict-free.
//   kA1 : phase conj(ddtot[j]) + row digits 0..2, 64x64 tiles, in place.
//   kA2r: row digits 3..5 + Re(ddtot[i] * T) -> fp32 out.
// All math packed 2-wide with fma.rn.f32x2 (compute fp32).

typedef unsigned long long u64;
typedef unsigned int u32;
#define NQ 4096

__device__ float   g_P[2][4];                  // per side: C, SA, c2, S2sigma
__device__ float2  g_D[NQ];                    // ddtot phase table
__device__ __half2 g_S[(size_t)4 * NQ * NQ];   // 268 MB fp16 complex intermediate

// ---------------- packed f32x2 helpers ----------------
__device__ __forceinline__ u64 pk2(float a, float b){
    u64 r; asm("mov.b64 %0, {%1,%2};" : "=l"(r) : "f"(a), "f"(b)); return r;
}
__device__ __forceinline__ void upk2(u64 v, float& a, float& b){
    asm("mov.b64 {%0,%1}, %2;" : "=f"(a), "=f"(b) : "l"(v));
}
__device__ __forceinline__ u64 f2fma(u64 a, u64 b, u64 c){
    u64 d; asm("fma.rn.f32x2 %0, %1, %2, %3;" : "=l"(d) : "l"(a), "l"(b), "l"(c)); return d;
}
__device__ __forceinline__ u64 f2mul(u64 a, u64 b){
    u64 d; asm("mul.rn.f32x2 %0, %1, %2;" : "=l"(d) : "l"(a), "l"(b)); return d;
}
__device__ __forceinline__ u64 f2neg(u64 a){ return a ^ 0x8000000080000000ULL; }

struct C2 { u64 re, im; };   // pair of complex numbers, SoA across f32x2 lanes

// fp16 <-> packed-pair conversion (2 complex: columns c0, c1)
__device__ __forceinline__ C2 ld_h2pair(const __half2* p){
    uint2 raw = *reinterpret_cast<const uint2*>(p);
    __half2 h0 = *reinterpret_cast<__half2*>(&raw.x);   // (re0, im0)
    __half2 h1 = *reinterpret_cast<__half2*>(&raw.y);   // (re1, im1)
    float2 f0 = __half22float2(h0);
    float2 f1 = __half22float2(h1);
    C2 c; c.re = pk2(f0.x, f1.x); c.im = pk2(f0.y, f1.y); return c;
}
__device__ __forceinline__ void st_h2pair(__half2* p, const C2& c){
    float r0,r1,i0,i1;
    upk2(c.re, r0, r1); upk2(c.im, i0, i1);
    __half2 h0 = __floats2half2_rn(r0, i0);
    __half2 h1 = __floats2half2_rn(r1, i1);
    uint2 raw;
    raw.x = *reinterpret_cast<u32*>(&h0);
    raw.y = *reinterpret_cast<u32*>(&h1);
    *reinterpret_cast<uint2*>(p) = raw;
}

// Factored matrix params, both f32x2 lanes duplicated.
// stage A: y0 = C x0 + i SA x2 (pairs (0,2),(1,3))
// stage G: z_r = c2 y_r + i sg_r S2 y_{3-r}, sg = {+,-,-,+}
struct Mat { u64 C, SA, SAn, c2, S2p, S2n; };

__device__ __forceinline__ Mat load_mat(int tr){
    Mat M; const float* p = g_P[tr];
    M.C   = pk2(p[0],  p[0]);
    M.SA  = pk2(p[1],  p[1]);
    M.SAn = pk2(-p[1], -p[1]);
    M.c2  = pk2(p[2],  p[2]);
    M.S2p = pk2(p[3],  p[3]);
    M.S2n = pk2(-p[3], -p[3]);
    return M;
}

// stage A (complex input)
__device__ __forceinline__ void stA(const C2& a0, const C2& a1, const C2& a2,
                                    const C2& a3, C2* __restrict__ y, const Mat& M){
    y[0].re = f2fma(M.SAn, a2.im, f2mul(M.C, a0.re));
    y[0].im = f2fma(M.SA,  a2.re, f2mul(M.C, a0.im));
    y[2].re = f2fma(M.SAn, a0.im, f2mul(M.C, a2.re));
    y[2].im = f2fma(M.SA,  a0.re, f2mul(M.C, a2.im));
    y[1].re = f2fma(M.SAn, a3.im, f2mul(M.C, a1.re));
    y[1].im = f2fma(M.SA,  a3.re, f2mul(M.C, a1.im));
    y[3].re = f2fma(M.SAn, a1.im, f2mul(M.C, a3.re));
    y[3].im = f2fma(M.SA,  a1.re, f2mul(M.C, a3.im));
}

// stage G: z_r = c2 y_r + i sg_r S2 y_{3-r}
__device__ __forceinline__ void stG(const C2* __restrict__ y, C2* __restrict__ o,
                                    const Mat& M){
    o[0].re = f2fma(M.S2n, y[3].im, f2mul(M.c2, y[0].re));
    o[0].im = f2fma(M.S2p, y[3].re, f2mul(M.c2, y[0].im));
    o[1].re = f2fma(M.S2p, y[2].im, f2mul(M.c2, y[1].re));
    o[1].im = f2fma(M.S2n, y[2].re, f2mul(M.c2, y[1].im));
    o[2].re = f2fma(M.S2p, y[1].im, f2mul(M.c2, y[2].re));
    o[2].im = f2fma(M.S2n, y[1].re, f2mul(M.c2, y[2].im));
    o[3].re = f2fma(M.S2n, y[0].im, f2mul(M.c2, y[3].re));
    o[3].im = f2fma(M.S2p, y[0].re, f2mul(M.c2, y[3].im));
}

// full butterfly (no D): A then G
__device__ __forceinline__ void bflyAG(C2& a0, C2& a1, C2& a2, C2& a3, const Mat& M){
    C2 y[4], o[4];
    stA(a0,a1,a2,a3,y,M);
    stG(y,o,M);
    a0=o[0]; a1=o[1]; a2=o[2]; a3=o[3];
}

// real-input butterfly (first digit of kJ): xr packed reals, im = 0
__device__ __forceinline__ void bflyAGr(const u64* __restrict__ xr, C2* __restrict__ v,
                                        const Mat& M){
    C2 y[4];
    y[0].re = f2mul(M.C,  xr[0]); y[0].im = f2mul(M.SA, xr[2]);
    y[2].re = f2mul(M.C,  xr[2]); y[2].im = f2mul(M.SA, xr[0]);
    y[1].re = f2mul(M.C,  xr[1]); y[1].im = f2mul(M.SA, xr[3]);
    y[3].re = f2mul(M.C,  xr[3]); y[3].im = f2mul(M.SA, xr[1]);
    stG(y,v,M);
}

// two digits (stride 1 then stride 4 in the 16-element register set)
__device__ __forceinline__ void digits2AG(C2* __restrict__ v, const Mat& M){
#pragma unroll
    for(int g=0;g<4;g++) bflyAG(v[4*g],v[4*g+1],v[4*g+2],v[4*g+3], M);
#pragma unroll
    for(int g=0;g<4;g++) bflyAG(v[g],v[g+4],v[g+8],v[g+12], M);
}

// ---------------- K0: build factored params ----------------
__global__ void k_build(const float* __restrict__ w, long long wn){
    if (threadIdx.x != 0 || blockIdx.x != 0) return;
    if (wn < 5) return;
    const float WM = 0.63245553203367586f;   // sqrt(2/5)
    float th0=w[0]*WM, th1=w[1]*WM, th2=w[2]*WM;
    float Cs = cosf(0.5f*(th0+th1)), Ss = sinf(0.5f*(th0+th1));
    float c2 = cosf(0.5f*th2), s2 = sinf(0.5f*th2);
    // side 0: Up (rows).   A: y0 = C x0 - i Ss x2 -> SA = -Ss; G sigma = +1
    g_P[0][0]=Cs; g_P[0][1]=-Ss; g_P[0][2]=c2; g_P[0][3]= s2;
    // side 1: conj(Up) (columns). SA = +Ss; G sigma = -1
    g_P[1][0]=Cs; g_P[1][1]= Ss; g_P[1][2]=c2; g_P[1][3]=-s2;
}

// ---------------- K0b: D_tot phase table ----------------
// dd[c] = exp(-i*phi_c), phi = {e3+e4, e3-e4, -(e3-e4), -(e3+e4)};
// ddtot[v] = exp(-i * sum_k phi[digit_k(v)]) = (cos s, -sin s).
__global__ void k_phase(const float* __restrict__ w, long long wn){
    if (wn < 5) return;
    int j = blockIdx.x*256 + threadIdx.x;
    if (j >= NQ) return;
    const float WM = 0.63245553203367586f;
    float e3 = 0.5f*w[3]*WM, e4 = 0.5f*w[4]*WM;
    float phi[4] = { e3+e4, e3-e4, -(e3-e4), -(e3+e4) };
    float s = 0.f; int v = j;
#pragma unroll
    for(int k=0;k<6;k++){ s += phi[v&3]; v >>= 2; }
    g_D[j] = make_float2(cosf(s), -sinf(s));
}

// ---------------- kJ: ALL 6 column digits (A,G only), 2 rows/CTA ---------
// smem: XOR swizzle phys(j) = j ^ ((j>>4)&15); conflict-free all phases.
// f32x2 lanes pack rows (R0, R0+1). Output rows stored fp16 (no phase here;
// conj(ddtot[j]) is applied in kA1).
__global__ __launch_bounds__(256,2) void kJ(const float* __restrict__ x,
                                            long long xlimf){
    extern __shared__ u64 sm[];
    u64* sre = sm;
    u64* sim = sm + 4096;
    const Mat M = load_mat(1);                 // conj side
    int t = threadIdx.x;
    long long R0 = (long long)blockIdx.x * 2;
    if ((R0 + 2) * 4096LL > xlimf) return;
    const float* x0 = x + R0*NQ;
    const float* x1 = x0 + NQ;
    int tl = t & 15;
    C2 v[16];
    // phase 1: digits strides 1,4  (j = 16t + k); phys = 16t + (k ^ tl)
    {
        u64 xr[16];
        int jb = t*16;
#pragma unroll
        for(int q=0;q<4;q++){
            float4 a  = *reinterpret_cast<const float4*>(x0 + jb + 4*q);
            float4 bb = *reinterpret_cast<const float4*>(x1 + jb + 4*q);
            xr[4*q+0]=pk2(a.x,bb.x); xr[4*q+1]=pk2(a.y,bb.y);
            xr[4*q+2]=pk2(a.z,bb.z); xr[4*q+3]=pk2(a.w,bb.w);
        }
#pragma unroll
        for(int g=0;g<4;g++) bflyAGr(xr+4*g, v+4*g, M);                 // digit 0 (real in)
#pragma unroll
        for(int g=0;g<4;g++) bflyAG(v[g],v[g+4],v[g+8],v[g+12], M);     // digit 1
#pragma unroll
        for(int k=0;k<16;k++){ int p = jb + (k ^ tl); sre[p]=v[k].re; sim[p]=v[k].im; }
    }
    __syncthreads();
    // phase 2: digits strides 16,64  (j = low + 16m + 256top); phys ^= m
    {
        int base = tl + 256*(t>>4);
#pragma unroll
        for(int m=0;m<16;m++){ int p=(base+16*m)^m; v[m].re=sre[p]; v[m].im=sim[p]; }
        digits2AG(v, M);
#pragma unroll
        for(int m=0;m<16;m++){ int p=(base+16*m)^m; sre[p]=v[m].re; sim[p]=v[m].im; }
    }
    __syncthreads();
    // phase 3: digits strides 256,1024  (j = t + 256m); fp16 row stores
    {
        int b3 = t ^ ((t>>4)&15);
#pragma unroll
        for(int m=0;m<16;m++){ int p=b3+256*m; v[m].re=sre[p]; v[m].im=sim[p]; }
        digits2AG(v, M);
        __half2* Y0 = g_S + R0*NQ;
        __half2* Y1 = Y0 + NQ;
#pragma unroll
        for(int m=0;m<16;m++){
            int j = t + 256*m;
            float r0,r1,i0,i1;
            upk2(v[m].re,r0,r1); upk2(v[m].im,i0,i1);
            Y0[j] = __floats2half2_rn(r0, i0);
            Y1[j] = __floats2half2_rn(r1, i1);
        }
    }
}

// ---------------- kA1: col phase + row digits 0..2, 64x64 tiles ----------
__global__ __launch_bounds__(128) void kA1(){
    __half2* __restrict__ p = g_S;
    __shared__ u64 sre[2048];
    __shared__ u64 sim[2048];
    const Mat M = load_mat(0);                 // Up side
    int t = threadIdx.x;
    long long base = ((long long)(blockIdx.z*4096 + blockIdx.y*64))*4096LL + blockIdx.x*64;
    int jp = t & 31;
    int g  = t >> 5;
    // column phase q = conj(ddtot[j]) for lanes j0 = jb+2jp, j1 = j0+1
    int j0 = blockIdx.x*64 + 2*jp;
    float2 qa = g_D[j0], qb = g_D[j0+1];
    u64 qre  = pk2(qa.x, qb.x);
    u64 qim  = pk2(qa.y, qb.y);     // ddtot.im; conj has -im
    u64 qimn = f2neg(qim);
    C2 v[16];
#pragma unroll
    for(int k=0;k<16;k++){
        long long m = 16*g + k;
        C2 c = ld_h2pair(p + base + m*4096 + 2*jp);
        // v = c * conj(q): re = cre*qre + cim*qim ; im = cim*qre - cre*qim
        v[k].re = f2fma(qim,  c.im, f2mul(qre, c.re));
        v[k].im = f2fma(qimn, c.re, f2mul(qre, c.im));
    }
    digits2AG(v, M);
#pragma unroll
    for(int k=0;k<16;k++){ int m=16*g+k; sre[m*32+jp]=v[k].re; sim[m*32+jp]=v[k].im; }
    __syncthreads();
    int lo0 = g*4;
#pragma unroll
    for(int q=0;q<4;q++){
        int lo = lo0 + q;
        C2 wv[4];
#pragma unroll
        for(int mm=0;mm<4;mm++){ int m=lo+16*mm; wv[mm].re=sre[m*32+jp]; wv[mm].im=sim[m*32+jp]; }
        bflyAG(wv[0],wv[1],wv[2],wv[3], M);
#pragma unroll
        for(int mm=0;mm<4;mm++){
            long long m = lo + 16*mm;
            st_h2pair(p + base + m*4096 + 2*jp, wv[mm]);
        }
    }
}

// ---------------- kA2r: row digits 3..5 + Re(ddtot[i] * T) ---------------
__global__ __launch_bounds__(128) void kA2r(float* __restrict__ outf,
                                            long long olimf){
    constexpr long long CS = 262144;           // 64 * 4096
    const __half2* __restrict__ p = g_S;
    __shared__ u64 sre[2048];
    __shared__ u64 sim[2048];
    const Mat M = load_mat(0);                 // Up side
    int t = threadIdx.x;
    int iy = blockIdx.y;                       // low row offset
    long long base = ((long long)(blockIdx.z*4096 + iy))*4096LL + blockIdx.x*64;
    if (base + 63*CS + 64 > olimf) return;
    int jp = t & 31;
    int g  = t >> 5;
    C2 v[16];
#pragma unroll
    for(int k=0;k<16;k++){
        long long m = 16*g + k;
        v[k] = ld_h2pair(p + base + m*CS + 2*jp);
    }
    digits2AG(v, M);
#pragma unroll
    for(int k=0;k<16;k++){ int m=16*g+k; sre[m*32+jp]=v[k].re; sim[m*32+jp]=v[k].im; }
    __syncthreads();
    int lo0 = g*4;
#pragma unroll
    for(int q=0;q<4;q++){
        int lo = lo0 + q;
        C2 wv[4];
#pragma unroll
        for(int mm=0;mm<4;mm++){ int m=lo+16*mm; wv[mm].re=sre[m*32+jp]; wv[mm].im=sim[m*32+jp]; }
        bflyAG(wv[0],wv[1],wv[2],wv[3], M);
#pragma unroll
        for(int mm=0;mm<4;mm++){
            long long m = lo + 16*mm;
            // row phase: out = Re(ddtot[i] * T) = a.re*T.re - a.im*T.im
            float2 a = g_D[iy + 64*(int)m];
            u64 areP = pk2(a.x, a.x);
            u64 aimN = pk2(-a.y, -a.y);
            u64 res = f2fma(aimN, wv[mm].im, f2mul(areP, wv[mm].re));
            float r0, r1;
            upk2(res, r0, r1);
            *reinterpret_cast<float2*>(outf + base + m*CS + 2*jp) = make_float2(r0, r1);
        }
    }
}

// ---------------- launch (sequential) ------------------------------------
extern "C" void kernel_launch(void* const* d_in, const int* in_sizes, int n_in,
                              void* d_out, int out_size){
    // identify inputs: w = smallest, x = largest
    int xi = 0, wi = 0;
    for (int i = 1; i < n_in; i++){
        if (in_sizes[i] > in_sizes[xi]) xi = i;
        if (in_sizes[i] < in_sizes[wi]) wi = i;
    }
    if (xi == wi && n_in >= 2) wi = (xi == 0) ? 1 : 0;
    const float* x = (const float*)d_in[xi];
    const float* w = (const float*)d_in[wi];
    long long xlim = (long long)in_sizes[xi];
    long long wlim = (long long)in_sizes[wi];
    long long olim = (long long)out_size;

    cudaFuncSetAttribute(kJ, cudaFuncAttributeMaxDynamicSharedMemorySize, 65536);

    k_build<<<1, 32>>>(w, wlim);
    k_phase<<<16, 256>>>(w, wlim);
    kJ<<<8192, 256, 65536>>>(x, xlim);                    // all 6 column digits (A,G)
    kA1<<<dim3(64, 64, 4), 128>>>();                      // col phase + row digits 0..2
    kA2r<<<dim3(64, 64, 4), 128>>>((float*)d_out, olim);  // row digits 3..5 + Re(phase)
}

// round 13
// speedup vs baseline: 1.0549x; 1.0549x over previous
#include <cuda_runtime.h>
#include <cuda_fp16.h>

// QuConv: out = Re(U X U^dagger), U = Up^{kron 6}, Up 4x4 complex from 5
// weights, X real [4,4096,4096]. Output: float32 real parts (67,108,864 el).
//
// R11 structure (best known: 372.8us). Fused D*G*A butterflies (D folded
// into precomputed constants — free). fp16 complex intermediate (268 MB).
//   kJ  : ALL 6 column digits (conj(Up)), full 4096-row in 64KB smem,
//         x(fp32) -> g_S(fp16). XOR-swizzled smem. Latency-bound ~180us.
//   kA1 : row digits 0..2 (Up), 64x64 tiles, in place on g_S.
//   kA2r: row digits 3..5 (Up), stride-64 tiles, Re-only fp32 stores.
// R13 delta: kA1/kA2r batch all 16 global loads into a raw staging array
// BEFORE the convert/compute loop (guaranteed MLP-16 per thread).

typedef unsigned long long u64;
typedef unsigned int u32;
#define NQ 4096

__device__ float   g_P[2][18];                 // [0]=Up params, [1]=conj(Up)
__device__ __half2 g_S[(size_t)4 * NQ * NQ];   // 268 MB fp16 complex intermediate

// ---------------- packed f32x2 helpers ----------------
__device__ __forceinline__ u64 pk2(float a, float b){
    u64 r; asm("mov.b64 %0, {%1,%2};" : "=l"(r) : "f"(a), "f"(b)); return r;
}
__device__ __forceinline__ void upk2(u64 v, float& a, float& b){
    asm("mov.b64 {%0,%1}, %2;" : "=f"(a), "=f"(b) : "l"(v));
}
__device__ __forceinline__ u64 f2fma(u64 a, u64 b, u64 c){
    u64 d; asm("fma.rn.f32x2 %0, %1, %2, %3;" : "=l"(d) : "l"(a), "l"(b), "l"(c)); return d;
}
__device__ __forceinline__ u64 f2mul(u64 a, u64 b){
    u64 d; asm("mul.rn.f32x2 %0, %1, %2;" : "=l"(d) : "l"(a), "l"(b)); return d;
}
__device__ __forceinline__ u64 f2neg(u64 a){ return a ^ 0x8000000080000000ULL; }

struct C2 { u64 re, im; };   // pair of complex numbers, SoA across f32x2 lanes

// raw fp16 pair -> packed f32x2 pair
__device__ __forceinline__ C2 cvt_h2pair(uint2 raw){
    __half2 h0 = *reinterpret_cast<__half2*>(&raw.x);   // (re0, im0)
    __half2 h1 = *reinterpret_cast<__half2*>(&raw.y);   // (re1, im1)
    float2 f0 = __half22float2(h0);
    float2 f1 = __half22float2(h1);
    C2 c; c.re = pk2(f0.x, f1.x); c.im = pk2(f0.y, f1.y); return c;
}
__device__ __forceinline__ void st_h2pair(__half2* p, const C2& c){
    float r0,r1,i0,i1;
    upk2(c.re, r0, r1); upk2(c.im, i0, i1);
    __half2 h0 = __floats2half2_rn(r0, i0);
    __half2 h1 = __floats2half2_rn(r1, i1);
    uint2 raw;
    raw.x = *reinterpret_cast<u32*>(&h0);
    raw.y = *reinterpret_cast<u32*>(&h1);
    *reinterpret_cast<uint2*>(p) = raw;
}

// Factored matrix params (entries duplicated across both f32x2 lanes).
// Stage A: y0 = C x0 + i SA x2 (pairs (0,2),(1,3)); stage DG: z_r = al_r y_r + be_r y_{3-r}.
struct Mat { u64 C, SA, SAn, alr[4], ali[4], ber[4], bei[4]; };

__device__ __forceinline__ Mat load_mat(int tr){
    Mat M; const float* p = g_P[tr];
    M.C   = pk2(p[0], p[0]);
    M.SA  = pk2(p[1], p[1]);
    M.SAn = pk2(-p[1], -p[1]);
#pragma unroll
    for(int r=0;r<4;r++){
        M.alr[r] = pk2(p[2+r],  p[2+r]);
        M.ali[r] = pk2(p[6+r],  p[6+r]);
        M.ber[r] = pk2(p[10+r], p[10+r]);
        M.bei[r] = pk2(p[14+r], p[14+r]);
    }
    return M;
}

// stage DG: out_r = al_r*y_r + be_r*y_{3-r}  (full complex)
__device__ __forceinline__ void dg4(const C2* __restrict__ y, C2* __restrict__ o,
                                    const Mat& M){
    u64 ny[4];
#pragma unroll
    for(int r=0;r<4;r++) ny[r] = f2neg(y[r].im);
#pragma unroll
    for(int r=0;r<4;r++){
        int rp = 3-r;
        u64 re = f2mul(M.alr[r], y[r].re);
        re = f2fma(M.ali[r], ny[r],     re);
        re = f2fma(M.ber[r], y[rp].re,  re);
        re = f2fma(M.bei[r], ny[rp],    re);
        u64 im = f2mul(M.alr[r], y[r].im);
        im = f2fma(M.ali[r], y[r].re,   im);
        im = f2fma(M.ber[r], y[rp].im,  im);
        im = f2fma(M.bei[r], y[rp].re,  im);
        o[r].re = re; o[r].im = im;
    }
}

// stage DG, real outputs only (final digit; output is Re)
__device__ __forceinline__ void dg4_re(const C2* __restrict__ y, u64* __restrict__ o,
                                       const Mat& M){
    u64 ny[4];
#pragma unroll
    for(int r=0;r<4;r++) ny[r] = f2neg(y[r].im);
#pragma unroll
    for(int r=0;r<4;r++){
        int rp = 3-r;
        u64 re = f2mul(M.alr[r], y[r].re);
        re = f2fma(M.ali[r], ny[r],    re);
        re = f2fma(M.ber[r], y[rp].re, re);
        re = f2fma(M.bei[r], ny[rp],   re);
        o[r] = re;
    }
}

// stage A (complex input)
__device__ __forceinline__ void stA(const C2& a0, const C2& a1, const C2& a2,
                                    const C2& a3, C2* __restrict__ y, const Mat& M){
    y[0].re = f2fma(M.SAn, a2.im, f2mul(M.C, a0.re));
    y[0].im = f2fma(M.SA,  a2.re, f2mul(M.C, a0.im));
    y[2].re = f2fma(M.SAn, a0.im, f2mul(M.C, a2.re));
    y[2].im = f2fma(M.SA,  a0.re, f2mul(M.C, a2.im));
    y[1].re = f2fma(M.SAn, a3.im, f2mul(M.C, a1.re));
    y[1].im = f2fma(M.SA,  a3.re, f2mul(M.C, a1.im));
    y[3].re = f2fma(M.SAn, a1.im, f2mul(M.C, a3.re));
    y[3].im = f2fma(M.SA,  a1.re, f2mul(M.C, a3.im));
}

__device__ __forceinline__ void bfly4f(C2& a0, C2& a1, C2& a2, C2& a3, const Mat& M){
    C2 y[4], o[4];
    stA(a0,a1,a2,a3,y,M);
    dg4(y,o,M);
    a0=o[0]; a1=o[1]; a2=o[2]; a3=o[3];
}

// real-input butterfly (first digit of kJ)
__device__ __forceinline__ void bfly4fr(const u64* __restrict__ xr, C2* __restrict__ v,
                                        const Mat& M){
    C2 y[4];
    y[0].re = f2mul(M.C,  xr[0]); y[0].im = f2mul(M.SA, xr[2]);
    y[2].re = f2mul(M.C,  xr[2]); y[2].im = f2mul(M.SA, xr[0]);
    y[1].re = f2mul(M.C,  xr[1]); y[1].im = f2mul(M.SA, xr[3]);
    y[3].re = f2mul(M.C,  xr[3]); y[3].im = f2mul(M.SA, xr[1]);
    dg4(y,v,M);
}

// two digits (stride 1 then stride 4 in the 16-element register set)
__device__ __forceinline__ void digits2f(C2* __restrict__ v, const Mat& M){
#pragma unroll
    for(int g=0;g<4;g++) bfly4f(v[4*g],v[4*g+1],v[4*g+2],v[4*g+3], M);
#pragma unroll
    for(int g=0;g<4;g++) bfly4f(v[g],v[g+4],v[g+8],v[g+12], M);
}

// ---------------- K0: build factored params from weights ----------------
__global__ void k_build(const float* __restrict__ w, long long wn){
    if (threadIdx.x != 0 || blockIdx.x != 0) return;
    if (wn < 5) return;
    const float WM = 0.63245553203367586f;   // sqrt(2/5)
    float th0=w[0]*WM, th1=w[1]*WM, th2=w[2]*WM, th3=w[3]*WM, th4=w[4]*WM;
    float Cs = cosf(0.5f*(th0+th1)), Ss = sinf(0.5f*(th0+th1));
    float c2 = cosf(0.5f*th2), s2 = sinf(0.5f*th2);
    float e3 = 0.5f*th3, e4 = 0.5f*th4;
    float ddx[4], ddy[4];
    ddx[0]=cosf(e3+e4); ddy[0]=-sinf(e3+e4);
    ddx[1]=cosf(e3-e4); ddy[1]=-sinf(e3-e4);
    ddx[2]= ddx[1];     ddy[2]=-ddy[1];
    ddx[3]= ddx[0];     ddy[3]=-ddy[0];
    const float sg[4] = {1.f,-1.f,-1.f,1.f};
    g_P[0][0]=Cs; g_P[0][1]=-Ss;   // Up
    g_P[1][0]=Cs; g_P[1][1]= Ss;   // conj(Up)
    for(int r=0;r<4;r++){
        float alx = ddx[r]*c2,        aly = ddy[r]*c2;
        float bex = -sg[r]*s2*ddy[r], bey = sg[r]*s2*ddx[r];
        g_P[0][2+r]=alx;  g_P[0][6+r]=aly;  g_P[0][10+r]=bex;  g_P[0][14+r]=bey;
        g_P[1][2+r]=alx;  g_P[1][6+r]=-aly; g_P[1][10+r]=bex;  g_P[1][14+r]=-bey;
    }
}

// ---------------- kJ: ALL 6 column digits, 2 rows/CTA --------------------
// smem: XOR swizzle phys(j) = j ^ ((j>>4)&15); conflict-free all phases.
// f32x2 lanes pack rows (R0, R0+1). Output rows stored fp16.
__global__ __launch_bounds__(256,2) void kJ(const float* __restrict__ x,
                                            long long xlimf){
    extern __shared__ u64 sm[];
    u64* sre = sm;
    u64* sim = sm + 4096;
    const Mat M = load_mat(1);                 // conj(Up)
    int t = threadIdx.x;
    long long R0 = (long long)blockIdx.x * 2;
    if ((R0 + 2) * 4096LL > xlimf) return;
    const float* x0 = x + R0*NQ;
    const float* x1 = x0 + NQ;
    int tl = t & 15;
    C2 v[16];
    // phase 1: digits strides 1,4  (j = 16t + k); phys = 16t + (k ^ tl)
    {
        u64 xr[16];
        int jb = t*16;
#pragma unroll
        for(int q=0;q<4;q++){
            float4 a  = *reinterpret_cast<const float4*>(x0 + jb + 4*q);
            float4 bb = *reinterpret_cast<const float4*>(x1 + jb + 4*q);
            xr[4*q+0]=pk2(a.x,bb.x); xr[4*q+1]=pk2(a.y,bb.y);
            xr[4*q+2]=pk2(a.z,bb.z); xr[4*q+3]=pk2(a.w,bb.w);
        }
#pragma unroll
        for(int g=0;g<4;g++) bfly4fr(xr+4*g, v+4*g, M);                 // digit 0 (real in)
#pragma unroll
        for(int g=0;g<4;g++) bfly4f(v[g],v[g+4],v[g+8],v[g+12], M);     // digit 1
#pragma unroll
        for(int k=0;k<16;k++){ int p = jb + (k ^ tl); sre[p]=v[k].re; sim[p]=v[k].im; }
    }
    __syncthreads();
    // phase 2: digits strides 16,64  (j = low + 16m + 256top); phys ^= m
    {
        int base = tl + 256*(t>>4);
#pragma unroll
        for(int m=0;m<16;m++){ int p=(base+16*m)^m; v[m].re=sre[p]; v[m].im=sim[p]; }
        digits2f(v, M);
#pragma unroll
        for(int m=0;m<16;m++){ int p=(base+16*m)^m; sre[p]=v[m].re; sim[p]=v[m].im; }
    }
    __syncthreads();
    // phase 3: digits strides 256,1024  (j = t + 256m); fp16 row stores
    {
        int b3 = t ^ ((t>>4)&15);
#pragma unroll
        for(int m=0;m<16;m++){ int p=b3+256*m; v[m].re=sre[p]; v[m].im=sim[p]; }
        digits2f(v, M);
        __half2* Y0 = g_S + R0*NQ;
        __half2* Y1 = Y0 + NQ;
#pragma unroll
        for(int m=0;m<16;m++){
            int j = t + 256*m;
            float r0,r1,i0,i1;
            upk2(v[m].re,r0,r1); upk2(v[m].im,i0,i1);
            Y0[j] = __floats2half2_rn(r0, i0);
            Y1[j] = __floats2half2_rn(r1, i1);
        }
    }
}

// ---------------- kA1: row digits 0..2, 64x64 coalesced tiles ------------
// Loads batched: 16 raw uint2 LDGs issued before any conversion/compute.
__global__ __launch_bounds__(128) void kA1(){
    __half2* __restrict__ p = g_S;
    __shared__ u64 sre[2048];
    __shared__ u64 sim[2048];
    const Mat M = load_mat(0);                 // Up
    int t = threadIdx.x;
    long long base = ((long long)(blockIdx.z*4096 + blockIdx.y*64))*4096LL + blockIdx.x*64;
    int jp = t & 31;
    int g  = t >> 5;
    uint2 raw[16];
#pragma unroll
    for(int k=0;k<16;k++){
        long long m = 16*g + k;
        raw[k] = *reinterpret_cast<const uint2*>(p + base + m*4096 + 2*jp);
    }
    C2 v[16];
#pragma unroll
    for(int k=0;k<16;k++) v[k] = cvt_h2pair(raw[k]);
    digits2f(v, M);
#pragma unroll
    for(int k=0;k<16;k++){ int m=16*g+k; sre[m*32+jp]=v[k].re; sim[m*32+jp]=v[k].im; }
    __syncthreads();
    int lo0 = g*4;
#pragma unroll
    for(int q=0;q<4;q++){
        int lo = lo0 + q;
        C2 wv[4];
#pragma unroll
        for(int mm=0;mm<4;mm++){ int m=lo+16*mm; wv[mm].re=sre[m*32+jp]; wv[mm].im=sim[m*32+jp]; }
        bfly4f(wv[0],wv[1],wv[2],wv[3], M);
#pragma unroll
        for(int mm=0;mm<4;mm++){
            long long m = lo + 16*mm;
            st_h2pair(p + base + m*4096 + 2*jp, wv[mm]);
        }
    }
}

// ---------------- kA2r: row digits 3..5, Re-only fp32 stores -------------
// Loads batched like kA1.
__global__ __launch_bounds__(128) void kA2r(float* __restrict__ outf,
                                            long long olimf){
    constexpr long long CS = 262144;           // 64 * 4096
    const __half2* __restrict__ p = g_S;
    __shared__ u64 sre[2048];
    __shared__ u64 sim[2048];
    const Mat M = load_mat(0);                 // Up
    int t = threadIdx.x;
    long long base = ((long long)(blockIdx.z*4096 + blockIdx.y))*4096LL + blockIdx.x*64;
    if (base + 63*CS + 64 > olimf) return;
    int jp = t & 31;
    int g  = t >> 5;
    uint2 raw[16];
#pragma unroll
    for(int k=0;k<16;k++){
        long long m = 16*g + k;
        raw[k] = *reinterpret_cast<const uint2*>(p + base + m*CS + 2*jp);
    }
    C2 v[16];
#pragma unroll
    for(int k=0;k<16;k++) v[k] = cvt_h2pair(raw[k]);
    digits2f(v, M);
#pragma unroll
    for(int k=0;k<16;k++){ int m=16*g+k; sre[m*32+jp]=v[k].re; sim[m*32+jp]=v[k].im; }
    __syncthreads();
    int lo0 = g*4;
#pragma unroll
    for(int q=0;q<4;q++){
        int lo = lo0 + q;
        C2 wv[4];
#pragma unroll
        for(int mm=0;mm<4;mm++){ int m=lo+16*mm; wv[mm].re=sre[m*32+jp]; wv[mm].im=sim[m*32+jp]; }
        C2 y[4]; u64 re4[4];
        stA(wv[0],wv[1],wv[2],wv[3], y, M);
        dg4_re(y, re4, M);
#pragma unroll
        for(int mm=0;mm<4;mm++){
            long long m = lo + 16*mm;
            float r0, r1;
            upk2(re4[mm], r0, r1);
            *reinterpret_cast<float2*>(outf + base + m*CS + 2*jp) = make_float2(r0, r1);
        }
    }
}

// ---------------- launch (sequential) ------------------------------------
extern "C" void kernel_launch(void* const* d_in, const int* in_sizes, int n_in,
                              void* d_out, int out_size){
    // identify inputs: w = smallest, x = largest
    int xi = 0, wi = 0;
    for (int i = 1; i < n_in; i++){
        if (in_sizes[i] > in_sizes[xi]) xi = i;
        if (in_sizes[i] < in_sizes[wi]) wi = i;
    }
    if (xi == wi && n_in >= 2) wi = (xi == 0) ? 1 : 0;
    const float* x = (const float*)d_in[xi];
    const float* w = (const float*)d_in[wi];
    long long xlim = (long long)in_sizes[xi];
    long long wlim = (long long)in_sizes[wi];
    long long olim = (long long)out_size;

    cudaFuncSetAttribute(kJ, cudaFuncAttributeMaxDynamicSharedMemorySize, 65536);

    k_build<<<1, 32>>>(w, wlim);
    kJ<<<8192, 256, 65536>>>(x, xlim);                    // all 6 column digits
    kA1<<<dim3(64, 64, 4), 128>>>();                      // row digits 0..2
    kA2r<<<dim3(64, 64, 4), 128>>>((float*)d_out, olim);  // row digits 3..5 -> Re
}

// round 14
// speedup vs baseline: 1.0792x; 1.0231x over previous
#include <cuda_runtime.h>
#include <cuda_fp16.h>

// QuConv: out = Re(U X U^dagger), U = Up^{kron 6}, Up 4x4 complex from 5
// weights, X real [4,4096,4096]. Output: float32 real parts (67,108,864 el).
//
// kJ  : ALL 6 column digits via A,G stages only (diagonals pulled out into
//       one multiply by conj(ddtot[j]) at store), 64KB XOR-swizzled smem,
//       __launch_bounds__(256,3) for 24 warps/SM. x(fp32) -> g_S(fp16).
// kA1 : row digits 0..2 (fused D*G*A, self-contained), 64x64 tiles, in place.
// kA2r: row digits 3..5 (fused), stride-64 tiles, Re-only fp32 stores.
// fp16 complex intermediate (268 MB); all math packed 2-wide fma.rn.f32x2.

typedef unsigned long long u64;
typedef unsigned int u32;
#define NQ 4096

__device__ float   g_P[2][18];                 // fused DGA params (kA kernels)
__device__ float   g_PAG[2][4];                // AG params: C, SA, c2, S2sigma
__device__ float2  g_D[NQ];                    // ddtot phase table
__device__ __half2 g_S[(size_t)4 * NQ * NQ];   // 268 MB fp16 complex intermediate

// ---------------- packed f32x2 helpers ----------------
__device__ __forceinline__ u64 pk2(float a, float b){
    u64 r; asm("mov.b64 %0, {%1,%2};" : "=l"(r) : "f"(a), "f"(b)); return r;
}
__device__ __forceinline__ void upk2(u64 v, float& a, float& b){
    asm("mov.b64 {%0,%1}, %2;" : "=f"(a), "=f"(b) : "l"(v));
}
__device__ __forceinline__ u64 f2fma(u64 a, u64 b, u64 c){
    u64 d; asm("fma.rn.f32x2 %0, %1, %2, %3;" : "=l"(d) : "l"(a), "l"(b), "l"(c)); return d;
}
__device__ __forceinline__ u64 f2mul(u64 a, u64 b){
    u64 d; asm("mul.rn.f32x2 %0, %1, %2;" : "=l"(d) : "l"(a), "l"(b)); return d;
}
__device__ __forceinline__ u64 f2neg(u64 a){ return a ^ 0x8000000080000000ULL; }

struct C2 { u64 re, im; };   // pair of complex numbers, SoA across f32x2 lanes

__device__ __forceinline__ C2 cvt_h2pair(uint2 raw){
    __half2 h0 = *reinterpret_cast<__half2*>(&raw.x);
    __half2 h1 = *reinterpret_cast<__half2*>(&raw.y);
    float2 f0 = __half22float2(h0);
    float2 f1 = __half22float2(h1);
    C2 c; c.re = pk2(f0.x, f1.x); c.im = pk2(f0.y, f1.y); return c;
}
__device__ __forceinline__ void st_h2pair(__half2* p, const C2& c){
    float r0,r1,i0,i1;
    upk2(c.re, r0, r1); upk2(c.im, i0, i1);
    __half2 h0 = __floats2half2_rn(r0, i0);
    __half2 h1 = __floats2half2_rn(r1, i1);
    uint2 raw;
    raw.x = *reinterpret_cast<u32*>(&h0);
    raw.y = *reinterpret_cast<u32*>(&h1);
    *reinterpret_cast<uint2*>(p) = raw;
}

// ======== fused DGA butterfly machinery (kA kernels — unchanged) ========
struct Mat { u64 C, SA, SAn, alr[4], ali[4], ber[4], bei[4]; };

__device__ __forceinline__ Mat load_mat(int tr){
    Mat M; const float* p = g_P[tr];
    M.C   = pk2(p[0], p[0]);
    M.SA  = pk2(p[1], p[1]);
    M.SAn = pk2(-p[1], -p[1]);
#pragma unroll
    for(int r=0;r<4;r++){
        M.alr[r] = pk2(p[2+r],  p[2+r]);
        M.ali[r] = pk2(p[6+r],  p[6+r]);
        M.ber[r] = pk2(p[10+r], p[10+r]);
        M.bei[r] = pk2(p[14+r], p[14+r]);
    }
    return M;
}

__device__ __forceinline__ void dg4(const C2* __restrict__ y, C2* __restrict__ o,
                                    const Mat& M){
    u64 ny[4];
#pragma unroll
    for(int r=0;r<4;r++) ny[r] = f2neg(y[r].im);
#pragma unroll
    for(int r=0;r<4;r++){
        int rp = 3-r;
        u64 re = f2mul(M.alr[r], y[r].re);
        re = f2fma(M.ali[r], ny[r],     re);
        re = f2fma(M.ber[r], y[rp].re,  re);
        re = f2fma(M.bei[r], ny[rp],    re);
        u64 im = f2mul(M.alr[r], y[r].im);
        im = f2fma(M.ali[r], y[r].re,   im);
        im = f2fma(M.ber[r], y[rp].im,  im);
        im = f2fma(M.bei[r], y[rp].re,  im);
        o[r].re = re; o[r].im = im;
    }
}

__device__ __forceinline__ void dg4_re(const C2* __restrict__ y, u64* __restrict__ o,
                                       const Mat& M){
    u64 ny[4];
#pragma unroll
    for(int r=0;r<4;r++) ny[r] = f2neg(y[r].im);
#pragma unroll
    for(int r=0;r<4;r++){
        int rp = 3-r;
        u64 re = f2mul(M.alr[r], y[r].re);
        re = f2fma(M.ali[r], ny[r],    re);
        re = f2fma(M.ber[r], y[rp].re, re);
        re = f2fma(M.bei[r], ny[rp],   re);
        o[r] = re;
    }
}

__device__ __forceinline__ void stA(const C2& a0, const C2& a1, const C2& a2,
                                    const C2& a3, C2* __restrict__ y, const Mat& M){
    y[0].re = f2fma(M.SAn, a2.im, f2mul(M.C, a0.re));
    y[0].im = f2fma(M.SA,  a2.re, f2mul(M.C, a0.im));
    y[2].re = f2fma(M.SAn, a0.im, f2mul(M.C, a2.re));
    y[2].im = f2fma(M.SA,  a0.re, f2mul(M.C, a2.im));
    y[1].re = f2fma(M.SAn, a3.im, f2mul(M.C, a1.re));
    y[1].im = f2fma(M.SA,  a3.re, f2mul(M.C, a1.im));
    y[3].re = f2fma(M.SAn, a1.im, f2mul(M.C, a3.re));
    y[3].im = f2fma(M.SA,  a1.re, f2mul(M.C, a3.im));
}

__device__ __forceinline__ void bfly4f(C2& a0, C2& a1, C2& a2, C2& a3, const Mat& M){
    C2 y[4], o[4];
    stA(a0,a1,a2,a3,y,M);
    dg4(y,o,M);
    a0=o[0]; a1=o[1]; a2=o[2]; a3=o[3];
}

__device__ __forceinline__ void digits2f(C2* __restrict__ v, const Mat& M){
#pragma unroll
    for(int g=0;g<4;g++) bfly4f(v[4*g],v[4*g+1],v[4*g+2],v[4*g+3], M);
#pragma unroll
    for(int g=0;g<4;g++) bfly4f(v[g],v[g+4],v[g+8],v[g+12], M);
}

// ======== AG butterfly machinery (kJ — small register footprint) ========
struct MatAG { u64 C, SA, SAn, c2, S2p, S2n; };

__device__ __forceinline__ MatAG load_matAG(int tr){
    MatAG M; const float* p = g_PAG[tr];
    M.C   = pk2(p[0],  p[0]);
    M.SA  = pk2(p[1],  p[1]);
    M.SAn = pk2(-p[1], -p[1]);
    M.c2  = pk2(p[2],  p[2]);
    M.S2p = pk2(p[3],  p[3]);
    M.S2n = pk2(-p[3], -p[3]);
    return M;
}

__device__ __forceinline__ void stA_ag(const C2& a0, const C2& a1, const C2& a2,
                                       const C2& a3, C2* __restrict__ y, const MatAG& M){
    y[0].re = f2fma(M.SAn, a2.im, f2mul(M.C, a0.re));
    y[0].im = f2fma(M.SA,  a2.re, f2mul(M.C, a0.im));
    y[2].re = f2fma(M.SAn, a0.im, f2mul(M.C, a2.re));
    y[2].im = f2fma(M.SA,  a0.re, f2mul(M.C, a2.im));
    y[1].re = f2fma(M.SAn, a3.im, f2mul(M.C, a1.re));
    y[1].im = f2fma(M.SA,  a3.re, f2mul(M.C, a1.im));
    y[3].re = f2fma(M.SAn, a1.im, f2mul(M.C, a3.re));
    y[3].im = f2fma(M.SA,  a1.re, f2mul(M.C, a3.im));
}

// stage G: z_r = c2 y_r + i sg_r S2 y_{3-r}, sg = {+,-,-,+}
__device__ __forceinline__ void stG(const C2* __restrict__ y, C2* __restrict__ o,
                                    const MatAG& M){
    o[0].re = f2fma(M.S2n, y[3].im, f2mul(M.c2, y[0].re));
    o[0].im = f2fma(M.S2p, y[3].re, f2mul(M.c2, y[0].im));
    o[1].re = f2fma(M.S2p, y[2].im, f2mul(M.c2, y[1].re));
    o[1].im = f2fma(M.S2n, y[2].re, f2mul(M.c2, y[1].im));
    o[2].re = f2fma(M.S2p, y[1].im, f2mul(M.c2, y[2].re));
    o[2].im = f2fma(M.S2n, y[1].re, f2mul(M.c2, y[2].im));
    o[3].re = f2fma(M.S2n, y[0].im, f2mul(M.c2, y[3].re));
    o[3].im = f2fma(M.S2p, y[0].re, f2mul(M.c2, y[3].im));
}

__device__ __forceinline__ void bflyAG(C2& a0, C2& a1, C2& a2, C2& a3, const MatAG& M){
    C2 y[4], o[4];
    stA_ag(a0,a1,a2,a3,y,M);
    stG(y,o,M);
    a0=o[0]; a1=o[1]; a2=o[2]; a3=o[3];
}

__device__ __forceinline__ void bflyAGr(const u64* __restrict__ xr, C2* __restrict__ v,
                                        const MatAG& M){
    C2 y[4];
    y[0].re = f2mul(M.C,  xr[0]); y[0].im = f2mul(M.SA, xr[2]);
    y[2].re = f2mul(M.C,  xr[2]); y[2].im = f2mul(M.SA, xr[0]);
    y[1].re = f2mul(M.C,  xr[1]); y[1].im = f2mul(M.SA, xr[3]);
    y[3].re = f2mul(M.C,  xr[3]); y[3].im = f2mul(M.SA, xr[1]);
    stG(y,v,M);
}

__device__ __forceinline__ void digits2AG(C2* __restrict__ v, const MatAG& M){
#pragma unroll
    for(int g=0;g<4;g++) bflyAG(v[4*g],v[4*g+1],v[4*g+2],v[4*g+3], M);
#pragma unroll
    for(int g=0;g<4;g++) bflyAG(v[g],v[g+4],v[g+8],v[g+12], M);
}

// ---------------- K0: build fused + AG params from weights ---------------
__global__ void k_build(const float* __restrict__ w, long long wn){
    if (threadIdx.x != 0 || blockIdx.x != 0) return;
    if (wn < 5) return;
    const float WM = 0.63245553203367586f;   // sqrt(2/5)
    float th0=w[0]*WM, th1=w[1]*WM, th2=w[2]*WM, th3=w[3]*WM, th4=w[4]*WM;
    float Cs = cosf(0.5f*(th0+th1)), Ss = sinf(0.5f*(th0+th1));
    float c2 = cosf(0.5f*th2), s2 = sinf(0.5f*th2);
    float e3 = 0.5f*th3, e4 = 0.5f*th4;
    float ddx[4], ddy[4];
    ddx[0]=cosf(e3+e4); ddy[0]=-sinf(e3+e4);
    ddx[1]=cosf(e3-e4); ddy[1]=-sinf(e3-e4);
    ddx[2]= ddx[1];     ddy[2]=-ddy[1];
    ddx[3]= ddx[0];     ddy[3]=-ddy[0];
    const float sg[4] = {1.f,-1.f,-1.f,1.f};
    // fused params (kA kernels)
    g_P[0][0]=Cs; g_P[0][1]=-Ss;   // Up
    g_P[1][0]=Cs; g_P[1][1]= Ss;   // conj(Up)
    for(int r=0;r<4;r++){
        float alx = ddx[r]*c2,        aly = ddy[r]*c2;
        float bex = -sg[r]*s2*ddy[r], bey = sg[r]*s2*ddx[r];
        g_P[0][2+r]=alx;  g_P[0][6+r]=aly;  g_P[0][10+r]=bex;  g_P[0][14+r]=bey;
        g_P[1][2+r]=alx;  g_P[1][6+r]=-aly; g_P[1][10+r]=bex;  g_P[1][14+r]=-bey;
    }
    // AG params (kJ)
    g_PAG[0][0]=Cs; g_PAG[0][1]=-Ss; g_PAG[0][2]=c2; g_PAG[0][3]= s2;  // Up side
    g_PAG[1][0]=Cs; g_PAG[1][1]= Ss; g_PAG[1][2]=c2; g_PAG[1][3]=-s2;  // conj side
}

// ---------------- K0b: D_tot phase table ----------------
// ddtot[v] = exp(-i * sum_k phi[digit_k(v)]) = (cos s, -sin s),
// phi = {e3+e4, e3-e4, -(e3-e4), -(e3+e4)}.
__global__ void k_phase(const float* __restrict__ w, long long wn){
    if (wn < 5) return;
    int j = blockIdx.x*256 + threadIdx.x;
    if (j >= NQ) return;
    const float WM = 0.63245553203367586f;
    float e3 = 0.5f*w[3]*WM, e4 = 0.5f*w[4]*WM;
    float phi[4] = { e3+e4, e3-e4, -(e3-e4), -(e3+e4) };
    float s = 0.f; int v = j;
#pragma unroll
    for(int k=0;k<6;k++){ s += phi[v&3]; v >>= 2; }
    g_D[j] = make_float2(cosf(s), -sinf(s));
}

// ---------------- kJ: ALL 6 column digits (AG) + conj(ddtot) epilogue ----
// smem: XOR swizzle phys(j) = j ^ ((j>>4)&15); conflict-free all phases.
// f32x2 lanes pack rows (R0, R0+1). 3 CTAs/SM target (85 regs).
__global__ __launch_bounds__(256,3) void kJ(const float* __restrict__ x,
                                            long long xlimf){
    extern __shared__ u64 sm[];
    u64* sre = sm;
    u64* sim = sm + 4096;
    const MatAG M = load_matAG(1);             // conj side
    int t = threadIdx.x;
    long long R0 = (long long)blockIdx.x * 2;
    if ((R0 + 2) * 4096LL > xlimf) return;
    const float* x0 = x + R0*NQ;
    const float* x1 = x0 + NQ;
    int tl = t & 15;
    C2 v[16];
    // phase 1: digits strides 1,4  (j = 16t + k); phys = 16t + (k ^ tl)
    {
        u64 xr[16];
        int jb = t*16;
#pragma unroll
        for(int q=0;q<4;q++){
            float4 a  = *reinterpret_cast<const float4*>(x0 + jb + 4*q);
            float4 bb = *reinterpret_cast<const float4*>(x1 + jb + 4*q);
            xr[4*q+0]=pk2(a.x,bb.x); xr[4*q+1]=pk2(a.y,bb.y);
            xr[4*q+2]=pk2(a.z,bb.z); xr[4*q+3]=pk2(a.w,bb.w);
        }
#pragma unroll
        for(int g=0;g<4;g++) bflyAGr(xr+4*g, v+4*g, M);                 // digit 0 (real in)
#pragma unroll
        for(int g=0;g<4;g++) bflyAG(v[g],v[g+4],v[g+8],v[g+12], M);     // digit 1
#pragma unroll
        for(int k=0;k<16;k++){ int p = jb + (k ^ tl); sre[p]=v[k].re; sim[p]=v[k].im; }
    }
    __syncthreads();
    // phase 2: digits strides 16,64  (j = low + 16m + 256top); phys ^= m
    {
        int base = tl + 256*(t>>4);
#pragma unroll
        for(int m=0;m<16;m++){ int p=(base+16*m)^m; v[m].re=sre[p]; v[m].im=sim[p]; }
        digits2AG(v, M);
#pragma unroll
        for(int m=0;m<16;m++){ int p=(base+16*m)^m; sre[p]=v[m].re; sim[p]=v[m].im; }
    }
    __syncthreads();
    // phase 3: digits strides 256,1024; epilogue conj(ddtot[j]); fp16 stores
    {
        int b3 = t ^ ((t>>4)&15);
#pragma unroll
        for(int m=0;m<16;m++){ int p=b3+256*m; v[m].re=sre[p]; v[m].im=sim[p]; }
        digits2AG(v, M);
        __half2* Y0 = g_S + R0*NQ;
        __half2* Y1 = Y0 + NQ;
#pragma unroll
        for(int m=0;m<16;m++){
            int j = t + 256*m;
            float2 q = g_D[j];                 // coalesced (consecutive t)
            u64 qre = pk2(q.x, q.x);
            u64 qim = pk2(q.y, q.y);
            // v * conj(q): re = vre*qre + vim*qim ; im = vim*qre - vre*qim
            u64 rre = f2fma(qim,        v[m].im, f2mul(qre, v[m].re));
            u64 rim = f2fma(f2neg(qim), v[m].re, f2mul(qre, v[m].im));
            float r0,r1,i0,i1;
            upk2(rre,r0,r1); upk2(rim,i0,i1);
            Y0[j] = __floats2half2_rn(r0, i0);
            Y1[j] = __floats2half2_rn(r1, i1);
        }
    }
}

// ---------------- kA1: row digits 0..2 (fused), 64x64 tiles --------------
__global__ __launch_bounds__(128) void kA1(){
    __half2* __restrict__ p = g_S;
    __shared__ u64 sre[2048];
    __shared__ u64 sim[2048];
    const Mat M = load_mat(0);                 // Up
    int t = threadIdx.x;
    long long base = ((long long)(blockIdx.z*4096 + blockIdx.y*64))*4096LL + blockIdx.x*64;
    int jp = t & 31;
    int g  = t >> 5;
    uint2 raw[16];
#pragma unroll
    for(int k=0;k<16;k++){
        long long m = 16*g + k;
        raw[k] = *reinterpret_cast<const uint2*>(p + base + m*4096 + 2*jp);
    }
    C2 v[16];
#pragma unroll
    for(int k=0;k<16;k++) v[k] = cvt_h2pair(raw[k]);
    digits2f(v, M);
#pragma unroll
    for(int k=0;k<16;k++){ int m=16*g+k; sre[m*32+jp]=v[k].re; sim[m*32+jp]=v[k].im; }
    __syncthreads();
    int lo0 = g*4;
#pragma unroll
    for(int q=0;q<4;q++){
        int lo = lo0 + q;
        C2 wv[4];
#pragma unroll
        for(int mm=0;mm<4;mm++){ int m=lo+16*mm; wv[mm].re=sre[m*32+jp]; wv[mm].im=sim[m*32+jp]; }
        bfly4f(wv[0],wv[1],wv[2],wv[3], M);
#pragma unroll
        for(int mm=0;mm<4;mm++){
            long long m = lo + 16*mm;
            st_h2pair(p + base + m*4096 + 2*jp, wv[mm]);
        }
    }
}

// ---------------- kA2r: row digits 3..5 (fused), Re-only fp32 stores -----
__global__ __launch_bounds__(128) void kA2r(float* __restrict__ outf,
                                            long long olimf){
    constexpr long long CS = 262144;           // 64 * 4096
    const __half2* __restrict__ p = g_S;
    __shared__ u64 sre[2048];
    __shared__ u64 sim[2048];
    const Mat M = load_mat(0);                 // Up
    int t = threadIdx.x;
    long long base = ((long long)(blockIdx.z*4096 + blockIdx.y))*4096LL + blockIdx.x*64;
    if (base + 63*CS + 64 > olimf) return;
    int jp = t & 31;
    int g  = t >> 5;
    uint2 raw[16];
#pragma unroll
    for(int k=0;k<16;k++){
        long long m = 16*g + k;
        raw[k] = *reinterpret_cast<const uint2*>(p + base + m*CS + 2*jp);
    }
    C2 v[16];
#pragma unroll
    for(int k=0;k<16;k++) v[k] = cvt_h2pair(raw[k]);
    digits2f(v, M);
#pragma unroll
    for(int k=0;k<16;k++){ int m=16*g+k; sre[m*32+jp]=v[k].re; sim[m*32+jp]=v[k].im; }
    __syncthreads();
    int lo0 = g*4;
#pragma unroll
    for(int q=0;q<4;q++){
        int lo = lo0 + q;
        C2 wv[4];
#pragma unroll
        for(int mm=0;mm<4;mm++){ int m=lo+16*mm; wv[mm].re=sre[m*32+jp]; wv[mm].im=sim[m*32+jp]; }
        C2 y[4]; u64 re4[4];
        stA(wv[0],wv[1],wv[2],wv[3], y, M);
        dg4_re(y, re4, M);
#pragma unroll
        for(int mm=0;mm<4;mm++){
            long long m = lo + 16*mm;
            float r0, r1;
            upk2(re4[mm], r0, r1);
            *reinterpret_cast<float2*>(outf + base + m*CS + 2*jp) = make_float2(r0, r1);
        }
    }
}

// ---------------- launch (sequential) ------------------------------------
extern "C" void kernel_launch(void* const* d_in, const int* in_sizes, int n_in,
                              void* d_out, int out_size){
    // identify inputs: w = smallest, x = largest
    int xi = 0, wi = 0;
    for (int i = 1; i < n_in; i++){
        if (in_sizes[i] > in_sizes[xi]) xi = i;
        if (in_sizes[i] < in_sizes[wi]) wi = i;
    }
    if (xi == wi && n_in >= 2) wi = (xi == 0) ? 1 : 0;
    const float* x = (const float*)d_in[xi];
    const float* w = (const float*)d_in[wi];
    long long xlim = (long long)in_sizes[xi];
    long long wlim = (long long)in_sizes[wi];
    long long olim = (long long)out_size;

    cudaFuncSetAttribute(kJ, cudaFuncAttributeMaxDynamicSharedMemorySize, 65536);

    k_build<<<1, 32>>>(w, wlim);
    k_phase<<<16, 256>>>(w, wlim);
    kJ<<<8192, 256, 65536>>>(x, xlim);                    // all 6 column digits (AG) + phase
    kA1<<<dim3(64, 64, 4), 128>>>();                      // row digits 0..2
    kA2r<<<dim3(64, 64, 4), 128>>>((float*)d_out, olim);  // row digits 3..5 -> Re
}

// round 15
// speedup vs baseline: 1.0859x; 1.0062x over previous
#include <cuda_runtime.h>
#include <cuda_fp16.h>

// QuConv: out = Re(U X U^dagger), U = Up^{kron 6}, Up 4x4 complex from 5
// weights, X real [4,4096,4096]. Output: float32 real parts (67,108,864 el).
//
// kJ  : ALL 6 column digits via A,G stages only (diagonals pulled out into
//       one multiply by conj(ddtot[j]) at store), 64KB XOR-swizzled smem,
//       __launch_bounds__(256,3) for 24 warps/SM. x(fp32) -> g_S(fp16).
// kA1 : row digits 0..2 (fused D*G*A, self-contained), 64x64 tiles, in place.
// kA2r: row digits 3..5 (fused), stride-64 tiles, Re-only fp32 stores.
// fp16 complex intermediate (268 MB); all math packed 2-wide fma.rn.f32x2.

typedef unsigned long long u64;
typedef unsigned int u32;
#define NQ 4096

__device__ float   g_P[2][18];                 // fused DGA params (kA kernels)
__device__ float   g_PAG[2][4];                // AG params: C, SA, c2, S2sigma
__device__ float2  g_D[NQ];                    // ddtot phase table
__device__ __half2 g_S[(size_t)4 * NQ * NQ];   // 268 MB fp16 complex intermediate

// ---------------- packed f32x2 helpers ----------------
__device__ __forceinline__ u64 pk2(float a, float b){
    u64 r; asm("mov.b64 %0, {%1,%2};" : "=l"(r) : "f"(a), "f"(b)); return r;
}
__device__ __forceinline__ void upk2(u64 v, float& a, float& b){
    asm("mov.b64 {%0,%1}, %2;" : "=f"(a), "=f"(b) : "l"(v));
}
__device__ __forceinline__ u64 f2fma(u64 a, u64 b, u64 c){
    u64 d; asm("fma.rn.f32x2 %0, %1, %2, %3;" : "=l"(d) : "l"(a), "l"(b), "l"(c)); return d;
}
__device__ __forceinline__ u64 f2mul(u64 a, u64 b){
    u64 d; asm("mul.rn.f32x2 %0, %1, %2;" : "=l"(d) : "l"(a), "l"(b)); return d;
}
__device__ __forceinline__ u64 f2neg(u64 a){ return a ^ 0x8000000080000000ULL; }

struct C2 { u64 re, im; };   // pair of complex numbers, SoA across f32x2 lanes

__device__ __forceinline__ C2 cvt_h2pair(uint2 raw){
    __half2 h0 = *reinterpret_cast<__half2*>(&raw.x);
    __half2 h1 = *reinterpret_cast<__half2*>(&raw.y);
    float2 f0 = __half22float2(h0);
    float2 f1 = __half22float2(h1);
    C2 c; c.re = pk2(f0.x, f1.x); c.im = pk2(f0.y, f1.y); return c;
}
__device__ __forceinline__ void st_h2pair(__half2* p, const C2& c){
    float r0,r1,i0,i1;
    upk2(c.re, r0, r1); upk2(c.im, i0, i1);
    __half2 h0 = __floats2half2_rn(r0, i0);
    __half2 h1 = __floats2half2_rn(r1, i1);
    uint2 raw;
    raw.x = *reinterpret_cast<u32*>(&h0);
    raw.y = *reinterpret_cast<u32*>(&h1);
    *reinterpret_cast<uint2*>(p) = raw;
}

// ======== fused DGA butterfly machinery (kA kernels — unchanged) ========
struct Mat { u64 C, SA, SAn, alr[4], ali[4], ber[4], bei[4]; };

__device__ __forceinline__ Mat load_mat(int tr){
    Mat M; const float* p = g_P[tr];
    M.C   = pk2(p[0], p[0]);
    M.SA  = pk2(p[1], p[1]);
    M.SAn = pk2(-p[1], -p[1]);
#pragma unroll
    for(int r=0;r<4;r++){
        M.alr[r] = pk2(p[2+r],  p[2+r]);
        M.ali[r] = pk2(p[6+r],  p[6+r]);
        M.ber[r] = pk2(p[10+r], p[10+r]);
        M.bei[r] = pk2(p[14+r], p[14+r]);
    }
    return M;
}

__device__ __forceinline__ void dg4(const C2* __restrict__ y, C2* __restrict__ o,
                                    const Mat& M){
    u64 ny[4];
#pragma unroll
    for(int r=0;r<4;r++) ny[r] = f2neg(y[r].im);
#pragma unroll
    for(int r=0;r<4;r++){
        int rp = 3-r;
        u64 re = f2mul(M.alr[r], y[r].re);
        re = f2fma(M.ali[r], ny[r],     re);
        re = f2fma(M.ber[r], y[rp].re,  re);
        re = f2fma(M.bei[r], ny[rp],    re);
        u64 im = f2mul(M.alr[r], y[r].im);
        im = f2fma(M.ali[r], y[r].re,   im);
        im = f2fma(M.ber[r], y[rp].im,  im);
        im = f2fma(M.bei[r], y[rp].re,  im);
        o[r].re = re; o[r].im = im;
    }
}

__device__ __forceinline__ void dg4_re(const C2* __restrict__ y, u64* __restrict__ o,
                                       const Mat& M){
    u64 ny[4];
#pragma unroll
    for(int r=0;r<4;r++) ny[r] = f2neg(y[r].im);
#pragma unroll
    for(int r=0;r<4;r++){
        int rp = 3-r;
        u64 re = f2mul(M.alr[r], y[r].re);
        re = f2fma(M.ali[r], ny[r],    re);
        re = f2fma(M.ber[r], y[rp].re, re);
        re = f2fma(M.bei[r], ny[rp],   re);
        o[r] = re;
    }
}

__device__ __forceinline__ void stA(const C2& a0, const C2& a1, const C2& a2,
                                    const C2& a3, C2* __restrict__ y, const Mat& M){
    y[0].re = f2fma(M.SAn, a2.im, f2mul(M.C, a0.re));
    y[0].im = f2fma(M.SA,  a2.re, f2mul(M.C, a0.im));
    y[2].re = f2fma(M.SAn, a0.im, f2mul(M.C, a2.re));
    y[2].im = f2fma(M.SA,  a0.re, f2mul(M.C, a2.im));
    y[1].re = f2fma(M.SAn, a3.im, f2mul(M.C, a1.re));
    y[1].im = f2fma(M.SA,  a3.re, f2mul(M.C, a1.im));
    y[3].re = f2fma(M.SAn, a1.im, f2mul(M.C, a3.re));
    y[3].im = f2fma(M.SA,  a1.re, f2mul(M.C, a3.im));
}

__device__ __forceinline__ void bfly4f(C2& a0, C2& a1, C2& a2, C2& a3, const Mat& M){
    C2 y[4], o[4];
    stA(a0,a1,a2,a3,y,M);
    dg4(y,o,M);
    a0=o[0]; a1=o[1]; a2=o[2]; a3=o[3];
}

__device__ __forceinline__ void digits2f(C2* __restrict__ v, const Mat& M){
#pragma unroll
    for(int g=0;g<4;g++) bfly4f(v[4*g],v[4*g+1],v[4*g+2],v[4*g+3], M);
#pragma unroll
    for(int g=0;g<4;g++) bfly4f(v[g],v[g+4],v[g+8],v[g+12], M);
}

// ======== AG butterfly machinery (kJ — small register footprint) ========
struct MatAG { u64 C, SA, SAn, c2, S2p, S2n; };

__device__ __forceinline__ MatAG load_matAG(int tr){
    MatAG M; const float* p = g_PAG[tr];
    M.C   = pk2(p[0],  p[0]);
    M.SA  = pk2(p[1],  p[1]);
    M.SAn = pk2(-p[1], -p[1]);
    M.c2  = pk2(p[2],  p[2]);
    M.S2p = pk2(p[3],  p[3]);
    M.S2n = pk2(-p[3], -p[3]);
    return M;
}

__device__ __forceinline__ void stA_ag(const C2& a0, const C2& a1, const C2& a2,
                                       const C2& a3, C2* __restrict__ y, const MatAG& M){
    y[0].re = f2fma(M.SAn, a2.im, f2mul(M.C, a0.re));
    y[0].im = f2fma(M.SA,  a2.re, f2mul(M.C, a0.im));
    y[2].re = f2fma(M.SAn, a0.im, f2mul(M.C, a2.re));
    y[2].im = f2fma(M.SA,  a0.re, f2mul(M.C, a2.im));
    y[1].re = f2fma(M.SAn, a3.im, f2mul(M.C, a1.re));
    y[1].im = f2fma(M.SA,  a3.re, f2mul(M.C, a1.im));
    y[3].re = f2fma(M.SAn, a1.im, f2mul(M.C, a3.re));
    y[3].im = f2fma(M.SA,  a1.re, f2mul(M.C, a3.im));
}

// stage G: z_r = c2 y_r + i sg_r S2 y_{3-r}, sg = {+,-,-,+}
__device__ __forceinline__ void stG(const C2* __restrict__ y, C2* __restrict__ o,
                                    const MatAG& M){
    o[0].re = f2fma(M.S2n, y[3].im, f2mul(M.c2, y[0].re));
    o[0].im = f2fma(M.S2p, y[3].re, f2mul(M.c2, y[0].im));
    o[1].re = f2fma(M.S2p, y[2].im, f2mul(M.c2, y[1].re));
    o[1].im = f2fma(M.S2n, y[2].re, f2mul(M.c2, y[1].im));
    o[2].re = f2fma(M.S2p, y[1].im, f2mul(M.c2, y[2].re));
    o[2].im = f2fma(M.S2n, y[1].re, f2mul(M.c2, y[2].im));
    o[3].re = f2fma(M.S2n, y[0].im, f2mul(M.c2, y[3].re));
    o[3].im = f2fma(M.S2p, y[0].re, f2mul(M.c2, y[3].im));
}

__device__ __forceinline__ void bflyAG(C2& a0, C2& a1, C2& a2, C2& a3, const MatAG& M){
    C2 y[4], o[4];
    stA_ag(a0,a1,a2,a3,y,M);
    stG(y,o,M);
    a0=o[0]; a1=o[1]; a2=o[2]; a3=o[3];
}

__device__ __forceinline__ void bflyAGr(const u64* __restrict__ xr, C2* __restrict__ v,
                                        const MatAG& M){
    C2 y[4];
    y[0].re = f2mul(M.C,  xr[0]); y[0].im = f2mul(M.SA, xr[2]);
    y[2].re = f2mul(M.C,  xr[2]); y[2].im = f2mul(M.SA, xr[0]);
    y[1].re = f2mul(M.C,  xr[1]); y[1].im = f2mul(M.SA, xr[3]);
    y[3].re = f2mul(M.C,  xr[3]); y[3].im = f2mul(M.SA, xr[1]);
    stG(y,v,M);
}

__device__ __forceinline__ void digits2AG(C2* __restrict__ v, const MatAG& M){
#pragma unroll
    for(int g=0;g<4;g++) bflyAG(v[4*g],v[4*g+1],v[4*g+2],v[4*g+3], M);
#pragma unroll
    for(int g=0;g<4;g++) bflyAG(v[g],v[g+4],v[g+8],v[g+12], M);
}

// ---------------- K0: build fused + AG params from weights ---------------
__global__ void k_build(const float* __restrict__ w, long long wn){
    if (threadIdx.x != 0 || blockIdx.x != 0) return;
    if (wn < 5) return;
    const float WM = 0.63245553203367586f;   // sqrt(2/5)
    float th0=w[0]*WM, th1=w[1]*WM, th2=w[2]*WM, th3=w[3]*WM, th4=w[4]*WM;
    float Cs = cosf(0.5f*(th0+th1)), Ss = sinf(0.5f*(th0+th1));
    float c2 = cosf(0.5f*th2), s2 = sinf(0.5f*th2);
    float e3 = 0.5f*th3, e4 = 0.5f*th4;
    float ddx[4], ddy[4];
    ddx[0]=cosf(e3+e4); ddy[0]=-sinf(e3+e4);
    ddx[1]=cosf(e3-e4); ddy[1]=-sinf(e3-e4);
    ddx[2]= ddx[1];     ddy[2]=-ddy[1];
    ddx[3]= ddx[0];     ddy[3]=-ddy[0];
    const float sg[4] = {1.f,-1.f,-1.f,1.f};
    // fused params (kA kernels)
    g_P[0][0]=Cs; g_P[0][1]=-Ss;   // Up
    g_P[1][0]=Cs; g_P[1][1]= Ss;   // conj(Up)
    for(int r=0;r<4;r++){
        float alx = ddx[r]*c2,        aly = ddy[r]*c2;
        float bex = -sg[r]*s2*ddy[r], bey = sg[r]*s2*ddx[r];
        g_P[0][2+r]=alx;  g_P[0][6+r]=aly;  g_P[0][10+r]=bex;  g_P[0][14+r]=bey;
        g_P[1][2+r]=alx;  g_P[1][6+r]=-aly; g_P[1][10+r]=bex;  g_P[1][14+r]=-bey;
    }
    // AG params (kJ)
    g_PAG[0][0]=Cs; g_PAG[0][1]=-Ss; g_PAG[0][2]=c2; g_PAG[0][3]= s2;  // Up side
    g_PAG[1][0]=Cs; g_PAG[1][1]= Ss; g_PAG[1][2]=c2; g_PAG[1][3]=-s2;  // conj side
}

// ---------------- K0b: D_tot phase table ----------------
// ddtot[v] = exp(-i * sum_k phi[digit_k(v)]) = (cos s, -sin s),
// phi = {e3+e4, e3-e4, -(e3-e4), -(e3+e4)}.
__global__ void k_phase(const float* __restrict__ w, long long wn){
    if (wn < 5) return;
    int j = blockIdx.x*256 + threadIdx.x;
    if (j >= NQ) return;
    const float WM = 0.63245553203367586f;
    float e3 = 0.5f*w[3]*WM, e4 = 0.5f*w[4]*WM;
    float phi[4] = { e3+e4, e3-e4, -(e3-e4), -(e3+e4) };
    float s = 0.f; int v = j;
#pragma unroll
    for(int k=0;k<6;k++){ s += phi[v&3]; v >>= 2; }
    g_D[j] = make_float2(cosf(s), -sinf(s));
}

// ---------------- kJ: ALL 6 column digits (AG) + conj(ddtot) epilogue ----
// smem: XOR swizzle phys(j) = j ^ ((j>>4)&15); conflict-free all phases.
// f32x2 lanes pack rows (R0, R0+1). 3 CTAs/SM target (85 regs).
__global__ __launch_bounds__(256,3) void kJ(const float* __restrict__ x,
                                            long long xlimf){
    extern __shared__ u64 sm[];
    u64* sre = sm;
    u64* sim = sm + 4096;
    const MatAG M = load_matAG(1);             // conj side
    int t = threadIdx.x;
    long long R0 = (long long)blockIdx.x * 2;
    if ((R0 + 2) * 4096LL > xlimf) return;
    const float* x0 = x + R0*NQ;
    const float* x1 = x0 + NQ;
    int tl = t & 15;
    C2 v[16];
    // phase 1: digits strides 1,4  (j = 16t + k); phys = 16t + (k ^ tl)
    {
        u64 xr[16];
        int jb = t*16;
#pragma unroll
        for(int q=0;q<4;q++){
            float4 a  = *reinterpret_cast<const float4*>(x0 + jb + 4*q);
            float4 bb = *reinterpret_cast<const float4*>(x1 + jb + 4*q);
            xr[4*q+0]=pk2(a.x,bb.x); xr[4*q+1]=pk2(a.y,bb.y);
            xr[4*q+2]=pk2(a.z,bb.z); xr[4*q+3]=pk2(a.w,bb.w);
        }
#pragma unroll
        for(int g=0;g<4;g++) bflyAGr(xr+4*g, v+4*g, M);                 // digit 0 (real in)
#pragma unroll
        for(int g=0;g<4;g++) bflyAG(v[g],v[g+4],v[g+8],v[g+12], M);     // digit 1
#pragma unroll
        for(int k=0;k<16;k++){ int p = jb + (k ^ tl); sre[p]=v[k].re; sim[p]=v[k].im; }
    }
    __syncthreads();
    // phase 2: digits strides 16,64  (j = low + 16m + 256top); phys ^= m
    {
        int base = tl + 256*(t>>4);
#pragma unroll
        for(int m=0;m<16;m++){ int p=(base+16*m)^m; v[m].re=sre[p]; v[m].im=sim[p]; }
        digits2AG(v, M);
#pragma unroll
        for(int m=0;m<16;m++){ int p=(base+16*m)^m; sre[p]=v[m].re; sim[p]=v[m].im; }
    }
    __syncthreads();
    // phase 3: digits strides 256,1024; epilogue conj(ddtot[j]); fp16 stores
    {
        int b3 = t ^ ((t>>4)&15);
#pragma unroll
        for(int m=0;m<16;m++){ int p=b3+256*m; v[m].re=sre[p]; v[m].im=sim[p]; }
        digits2AG(v, M);
        __half2* Y0 = g_S + R0*NQ;
        __half2* Y1 = Y0 + NQ;
#pragma unroll
        for(int m=0;m<16;m++){
            int j = t + 256*m;
            float2 q = g_D[j];                 // coalesced (consecutive t)
            u64 qre = pk2(q.x, q.x);
            u64 qim = pk2(q.y, q.y);
            // v * conj(q): re = vre*qre + vim*qim ; im = vim*qre - vre*qim
            u64 rre = f2fma(qim,        v[m].im, f2mul(qre, v[m].re));
            u64 rim = f2fma(f2neg(qim), v[m].re, f2mul(qre, v[m].im));
            float r0,r1,i0,i1;
            upk2(rre,r0,r1); upk2(rim,i0,i1);
            Y0[j] = __floats2half2_rn(r0, i0);
            Y1[j] = __floats2half2_rn(r1, i1);
        }
    }
}

// ---------------- kA1: row digits 0..2 (fused), 64x64 tiles --------------
__global__ __launch_bounds__(128) void kA1(){
    __half2* __restrict__ p = g_S;
    __shared__ u64 sre[2048];
    __shared__ u64 sim[2048];
    const Mat M = load_mat(0);                 // Up
    int t = threadIdx.x;
    long long base = ((long long)(blockIdx.z*4096 + blockIdx.y*64))*4096LL + blockIdx.x*64;
    int jp = t & 31;
    int g  = t >> 5;
    uint2 raw[16];
#pragma unroll
    for(int k=0;k<16;k++){
        long long m = 16*g + k;
        raw[k] = *reinterpret_cast<const uint2*>(p + base + m*4096 + 2*jp);
    }
    C2 v[16];
#pragma unroll
    for(int k=0;k<16;k++) v[k] = cvt_h2pair(raw[k]);
    digits2f(v, M);
#pragma unroll
    for(int k=0;k<16;k++){ int m=16*g+k; sre[m*32+jp]=v[k].re; sim[m*32+jp]=v[k].im; }
    __syncthreads();
    int lo0 = g*4;
#pragma unroll
    for(int q=0;q<4;q++){
        int lo = lo0 + q;
        C2 wv[4];
#pragma unroll
        for(int mm=0;mm<4;mm++){ int m=lo+16*mm; wv[mm].re=sre[m*32+jp]; wv[mm].im=sim[m*32+jp]; }
        bfly4f(wv[0],wv[1],wv[2],wv[3], M);
#pragma unroll
        for(int mm=0;mm<4;mm++){
            long long m = lo + 16*mm;
            st_h2pair(p + base + m*4096 + 2*jp, wv[mm]);
        }
    }
}

// ---------------- kA2r: row digits 3..5 (fused), Re-only fp32 stores -----
__global__ __launch_bounds__(128) void kA2r(float* __restrict__ outf,
                                            long long olimf){
    constexpr long long CS = 262144;           // 64 * 4096
    const __half2* __restrict__ p = g_S;
    __shared__ u64 sre[2048];
    __shared__ u64 sim[2048];
    const Mat M = load_mat(0);                 // Up
    int t = threadIdx.x;
    long long base = ((long long)(blockIdx.z*4096 + blockIdx.y))*4096LL + blockIdx.x*64;
    if (base + 63*CS + 64 > olimf) return;
    int jp = t & 31;
    int g  = t >> 5;
    uint2 raw[16];
#pragma unroll
    for(int k=0;k<16;k++){
        long long m = 16*g + k;
        raw[k] = *reinterpret_cast<const uint2*>(p + base + m*CS + 2*jp);
    }
    C2 v[16];
#pragma unroll
    for(int k=0;k<16;k++) v[k] = cvt_h2pair(raw[k]);
    digits2f(v, M);
#pragma unroll
    for(int k=0;k<16;k++){ int m=16*g+k; sre[m*32+jp]=v[k].re; sim[m*32+jp]=v[k].im; }
    __syncthreads();
    int lo0 = g*4;
#pragma unroll
    for(int q=0;q<4;q++){
        int lo = lo0 + q;
        C2 wv[4];
#pragma unroll
        for(int mm=0;mm<4;mm++){ int m=lo+16*mm; wv[mm].re=sre[m*32+jp]; wv[mm].im=sim[m*32+jp]; }
        C2 y[4]; u64 re4[4];
        stA(wv[0],wv[1],wv[2],wv[3], y, M);
        dg4_re(y, re4, M);
#pragma unroll
        for(int mm=0;mm<4;mm++){
            long long m = lo + 16*mm;
            float r0, r1;
            upk2(re4[mm], r0, r1);
            *reinterpret_cast<float2*>(outf + base + m*CS + 2*jp) = make_float2(r0, r1);
        }
    }
}

// ---------------- launch (sequential) ------------------------------------
extern "C" void kernel_launch(void* const* d_in, const int* in_sizes, int n_in,
                              void* d_out, int out_size){
    // identify inputs: w = smallest, x = largest
    int xi = 0, wi = 0;
    for (int i = 1; i < n_in; i++){
        if (in_sizes[i] > in_sizes[xi]) xi = i;
        if (in_sizes[i] < in_sizes[wi]) wi = i;
    }
    if (xi == wi && n_in >= 2) wi = (xi == 0) ? 1 : 0;
    const float* x = (const float*)d_in[xi];
    const float* w = (const float*)d_in[wi];
    long long xlim = (long long)in_sizes[xi];
    long long wlim = (long long)in_sizes[wi];
    long long olim = (long long)out_size;

    cudaFuncSetAttribute(kJ, cudaFuncAttributeMaxDynamicSharedMemorySize, 65536);

    k_build<<<1, 32>>>(w, wlim);
    k_phase<<<16, 256>>>(w, wlim);
    kJ<<<8192, 256, 65536>>>(x, xlim);                    // all 6 column digits (AG) + phase
    kA1<<<dim3(64, 64, 4), 128>>>();                      // row digits 0..2
    kA2r<<<dim3(64, 64, 4), 128>>>((float*)d_out, olim);  // row digits 3..5 -> Re
}